// round 17
// baseline (speedup 1.0000x reference)
#include <cuda_runtime.h>
#include <math.h>

#define IMG   112
#define CCH   192
#define TILE  28
#define HALO  3
#define HD    (TILE + 2*HALO)      // 34
#define NHP   (HD*HD)              // 1156 halo pixels
#define NT    512
#define NWARP (NT/32)              // 16
#define F4    (CCH/4)              // 48

__device__ __forceinline__ float hsum(float4 v) { return (v.x + v.y) + (v.z + v.w); }
__device__ __forceinline__ float hmax(float4 v) { return fmaxf(fmaxf(v.x, v.y), fmaxf(v.z, v.w)); }

__global__ __launch_bounds__(NT, 4)
void spatial_attn_fused(const float* __restrict__ x,
                        const float* __restrict__ w,
                        float* __restrict__ out)
{
    __shared__ float s_avg[NHP];
    __shared__ float s_max[NHP];
    __shared__ float s_att[TILE*TILE];
    __shared__ float s_w[98];

    const int tid  = threadIdx.x;
    const int warp = tid >> 5;
    const int lane = tid & 31;

    if (tid < 98) s_w[tid] = w[tid];

    // block -> (batch, tile_y, tile_x)
    const int TPR = IMG / TILE;              // 4
    int bidx = blockIdx.x;
    int b    = bidx / (TPR*TPR);
    int tr   = bidx % (TPR*TPR);
    int ty0  = (tr / TPR) * TILE;
    int tx0  = (tr % TPR) * TILE;

    const float* xb = x + (size_t)b * IMG * IMG * CCH;

    // ---- Phase 1: per-halo-pixel channel avg & max (one warp per pixel,
    //      float4 loads: lanes 0-31 take f4[0,32), lanes 0-15 take f4[32,48)) ----
    for (int p = warp; p < NHP; p += NWARP) {
        int hy = ty0 + p / HD - HALO;
        int wx = tx0 + p % HD - HALO;
        float s = 0.f, m = 0.f;
        if (hy >= 0 && hy < IMG && wx >= 0 && wx < IMG) {
            const float4* px4 = reinterpret_cast<const float4*>(xb + ((size_t)hy * IMG + wx) * CCH);
            float4 a = px4[lane];
            s = hsum(a);
            m = hmax(a);
            if (lane < 16) {
                float4 bq = px4[32 + lane];
                s += hsum(bq);
                m  = fmaxf(m, hmax(bq));
            }
            #pragma unroll
            for (int o = 16; o > 0; o >>= 1) {
                s += __shfl_xor_sync(0xffffffffu, s, o);
                m  = fmaxf(m, __shfl_xor_sync(0xffffffffu, m, o));
            }
        }
        if (lane == 0) {
            s_avg[p] = s * (1.0f / CCH);
            s_max[p] = m;
        }
    }
    __syncthreads();

    // ---- Phase 2: 7x7 conv (cross-correlation) + sigmoid ----
    for (int t = tid; t < TILE*TILE; t += NT) {
        int oy = t / TILE, ox = t % TILE;
        float acc = 0.f;
        #pragma unroll
        for (int kh = 0; kh < 7; kh++) {
            #pragma unroll
            for (int kw = 0; kw < 7; kw++) {
                int p = (oy + kh) * HD + (ox + kw);
                acc = fmaf(s_avg[p], s_w[(kh*7 + kw)*2 + 0], acc);
                acc = fmaf(s_max[p], s_w[(kh*7 + kw)*2 + 1], acc);
            }
        }
        s_att[t] = 1.0f / (1.0f + __expf(-acc));
    }
    __syncthreads();

    // ---- Phase 3: out = x * att; interior x re-read hits L2 (just loaded
    //      by phase 1); out written streaming. Guarded unroll-2. ----
    const int total4 = TILE*TILE*F4;         // 37632
    #pragma unroll 1
    for (int k = tid; k < total4; k += NT*2) {
        float4 v[2]; float a[2]; size_t g[2];
        int kk1 = k + NT;
        bool ok1 = (kk1 < total4);
        {
            int pt = k / F4;
            int c4 = k - pt * F4;
            int oy = pt / TILE, ox = pt - oy * TILE;
            g[0] = (((size_t)b * IMG + (ty0 + oy)) * IMG + (tx0 + ox)) * CCH + (size_t)c4 * 4;
            v[0] = *reinterpret_cast<const float4*>(x + g[0]);
            a[0] = s_att[pt];
        }
        if (ok1) {
            int pt = kk1 / F4;
            int c4 = kk1 - pt * F4;
            int oy = pt / TILE, ox = pt - oy * TILE;
            g[1] = (((size_t)b * IMG + (ty0 + oy)) * IMG + (tx0 + ox)) * CCH + (size_t)c4 * 4;
            v[1] = *reinterpret_cast<const float4*>(x + g[1]);
            a[1] = s_att[pt];
        }
        {
            float4 r = v[0]; float s = a[0];
            r.x *= s; r.y *= s; r.z *= s; r.w *= s;
            __stcs(reinterpret_cast<float4*>(out + g[0]), r);
        }
        if (ok1) {
            float4 r = v[1]; float s = a[1];
            r.x *= s; r.y *= s; r.z *= s; r.w *= s;
            __stcs(reinterpret_cast<float4*>(out + g[1]), r);
        }
    }
}

extern "C" void kernel_launch(void* const* d_in, const int* in_sizes, int n_in,
                              void* d_out, int out_size)
{
    const float* x = (const float*)d_in[0];
    const float* w = (const float*)d_in[1];
    float* out = (float*)d_out;

    const int TPR = IMG / TILE;              // 4
    dim3 grid(32 * TPR * TPR);               // 512 blocks, 512 threads, occ 4
    spatial_attn_fused<<<grid, NT>>>(x, w, out);
}